// round 2
// baseline (speedup 1.0000x reference)
#include <cuda_runtime.h>
#include <cstddef>

#define Bb 2
#define Ss 2048
#define Ee 1024
#define Hh 16
#define Dd 64
#define E3 3072

// Scratch (no allocations allowed in kernel_launch)
__device__ float g_qkv[Bb * Ss * E3];   // 48 MB: [B,S,3E] = Q|K|V
__device__ float g_attn[Bb * Ss * Ee];  // 16 MB: attention output in [B,S,E]

// ---------------------------------------------------------------------------
// Classic 128x128x8 register-blocked SGEMM with bias: C = A[MxK] @ W[KxN] + b
// 256 threads, 8x8 microtile per thread. M%128==0, N%128==0, K%8==0 assumed.
// ---------------------------------------------------------------------------
__device__ __forceinline__ void sgemm_body(
    const float* __restrict__ A, const float* __restrict__ W,
    const float* __restrict__ bias, float* __restrict__ C,
    int M, int N, int K)
{
    __shared__ float As[8][128];
    __shared__ float Wsm[8][128];

    const int tid = threadIdx.x;          // 0..255
    const int tx  = tid & 15;             // 0..15 (N dir)
    const int ty  = tid >> 4;             // 0..15 (M dir)

    const int a_row = tid >> 1;           // 0..127
    const int a_col = (tid & 1) * 4;      // 0 or 4
    const int w_row = tid >> 5;           // 0..7
    const int w_col = (tid & 31) * 4;     // 0..124

    const float* Ap = A + (size_t)(blockIdx.y * 128) * K;
    const float* Wp = W + blockIdx.x * 128;

    float acc[8][8];
#pragma unroll
    for (int i = 0; i < 8; i++)
#pragma unroll
        for (int j = 0; j < 8; j++) acc[i][j] = 0.f;

    for (int k0 = 0; k0 < K; k0 += 8) {
        float4 av = *(const float4*)(Ap + (size_t)a_row * K + k0 + a_col);
        As[a_col + 0][a_row] = av.x;
        As[a_col + 1][a_row] = av.y;
        As[a_col + 2][a_row] = av.z;
        As[a_col + 3][a_row] = av.w;
        *(float4*)&Wsm[w_row][w_col] =
            *(const float4*)(Wp + (size_t)(k0 + w_row) * N + w_col);
        __syncthreads();

#pragma unroll
        for (int k = 0; k < 8; k++) {
            float af[8], wf[8];
#pragma unroll
            for (int i = 0; i < 8; i++) af[i] = As[k][ty * 8 + i];
#pragma unroll
            for (int j = 0; j < 8; j++) wf[j] = Wsm[k][tx * 8 + j];
#pragma unroll
            for (int i = 0; i < 8; i++)
#pragma unroll
                for (int j = 0; j < 8; j++) acc[i][j] += af[i] * wf[j];
        }
        __syncthreads();
    }

    const int row0 = blockIdx.y * 128 + ty * 8;
    const int col0 = blockIdx.x * 128 + tx * 8;
#pragma unroll
    for (int i = 0; i < 8; i++) {
#pragma unroll
        for (int j = 0; j < 8; j += 4) {
            float4 v;
            v.x = acc[i][j + 0] + bias[col0 + j + 0];
            v.y = acc[i][j + 1] + bias[col0 + j + 1];
            v.z = acc[i][j + 2] + bias[col0 + j + 2];
            v.w = acc[i][j + 3] + bias[col0 + j + 3];
            *(float4*)(C + (size_t)(row0 + i) * N + col0 + j) = v;
        }
    }
}

__global__ __launch_bounds__(256) void qkv_gemm_kernel(
    const float* __restrict__ A, const float* __restrict__ W,
    const float* __restrict__ bias)
{
    sgemm_body(A, W, bias, g_qkv, Bb * Ss, E3, Ee);
}

__global__ __launch_bounds__(256) void proj_gemm_kernel(
    const float* __restrict__ W, const float* __restrict__ bias,
    float* __restrict__ C)
{
    sgemm_body(g_attn, W, bias, C, Bb * Ss, Ee, Ee);
}

// ---------------------------------------------------------------------------
// Flash-style causal attention, fp32.
// Grid: (S/64, B*H). Block: 64 threads, one thread per query row.
// K/V tiles of 32 rows staged in SMEM; broadcast LDS.128 in inner loops.
// Online softmax per thread (thread owns its whole row).
// ---------------------------------------------------------------------------
__global__ __launch_bounds__(64) void attn_kernel()
{
    __shared__ float Ks[32][64];
    __shared__ float Vs[32][64];

    const int qt  = blockIdx.x;           // 0..31
    const int bh  = blockIdx.y;           // 0..31
    const int b   = bh >> 4;
    const int h   = bh & 15;
    const int tid = threadIdx.x;          // 0..63
    const int qi  = qt * 64 + tid;        // global query index

    const float* base = g_qkv + (size_t)b * Ss * E3;

    // Load this thread's Q row into registers
    const float* qrow = base + (size_t)qi * E3 + h * Dd;
    float4 q[16];
#pragma unroll
    for (int i = 0; i < 16; i++) q[i] = ((const float4*)qrow)[i];

    float m = -1e30f, l = 0.f;
    float o[64];
#pragma unroll
    for (int d = 0; d < 64; d++) o[d] = 0.f;

    const int nkt = 2 * qt + 2;           // causal: key tiles 0..(2qt+1)
    for (int kt = 0; kt < nkt; kt++) {
        const float* kb = base + (size_t)(kt * 32) * E3 + Ee + h * Dd;
        const float* vb = kb + Ee;

        __syncthreads();   // protect previous tile's SMEM before overwrite
#pragma unroll
        for (int i = 0; i < 8; i++) {
            int idx = i * 64 + tid;       // 0..511 (float4 units)
            int r = idx >> 4;             // key row 0..31
            int c = idx & 15;             // float4 column 0..15
            ((float4*)Ks[r])[c] = ((const float4*)(kb + (size_t)r * E3))[c];
            ((float4*)Vs[r])[c] = ((const float4*)(vb + (size_t)r * E3))[c];
        }
        __syncthreads();

        // Scores for 32 keys
        float s[32];
#pragma unroll
        for (int j = 0; j < 32; j++) {
            float acc = 0.f;
#pragma unroll
            for (int i = 0; i < 16; i++) {
                float4 kv = ((const float4*)Ks[j])[i];
                acc += q[i].x * kv.x + q[i].y * kv.y +
                       q[i].z * kv.z + q[i].w * kv.w;
            }
            s[j] = acc * 0.125f;          // 1/sqrt(64)
        }

        // Causal mask within (partially) diagonal tiles
        const int lim = qi - kt * 32;     // largest valid j
        if (lim < 31) {
#pragma unroll
            for (int j = 0; j < 32; j++)
                if (j > lim) s[j] = -1e30f;
        }

        // Online softmax update
        float mt = m;
#pragma unroll
        for (int j = 0; j < 32; j++) mt = fmaxf(mt, s[j]);
        const float corr = __expf(m - mt);
        m = mt;
        l *= corr;
#pragma unroll
        for (int d = 0; d < 64; d++) o[d] *= corr;

#pragma unroll
        for (int j = 0; j < 32; j++) {
            const float p = __expf(s[j] - m);
            l += p;
#pragma unroll
            for (int i = 0; i < 16; i++) {
                float4 vv = ((const float4*)Vs[j])[i];
                o[4 * i + 0] += p * vv.x;
                o[4 * i + 1] += p * vv.y;
                o[4 * i + 2] += p * vv.z;
                o[4 * i + 3] += p * vv.w;
            }
        }
    }

    // Normalize and write to [B,S,E] layout (head h occupies cols h*64..h*64+63)
    const float inv = 1.f / l;
    float* orow = g_attn + ((size_t)b * Ss + qi) * Ee + h * Dd;
#pragma unroll
    for (int i = 0; i < 16; i++) {
        float4 v;
        v.x = o[4 * i + 0] * inv;
        v.y = o[4 * i + 1] * inv;
        v.z = o[4 * i + 2] * inv;
        v.w = o[4 * i + 3] * inv;
        ((float4*)orow)[i] = v;
    }
}

// ---------------------------------------------------------------------------
extern "C" void kernel_launch(void* const* d_in, const int* in_sizes, int n_in,
                              void* d_out, int out_size)
{
    const float* hs    = (const float*)d_in[0];  // hidden_states [B,S,E]
    const float* wqkv  = (const float*)d_in[1];  // c_attn_w [E,3E]
    const float* bqkv  = (const float*)d_in[2];  // c_attn_b [3E]
    const float* wproj = (const float*)d_in[3];  // c_proj_w [E,E]
    const float* bproj = (const float*)d_in[4];  // c_proj_b [E]
    float* out = (float*)d_out;                  // [B,S,E] fp32

    dim3 g1(E3 / 128, (Bb * Ss) / 128);          // 24 x 32
    qkv_gemm_kernel<<<g1, 256>>>(hs, wqkv, bqkv);

    dim3 g2(Ss / 64, Bb * Hh);                   // 32 x 32
    attn_kernel<<<g2, 64>>>();

    dim3 g3(Ee / 128, (Bb * Ss) / 128);          // 8 x 32
    proj_gemm_kernel<<<g3, 256>>>(wproj, bproj, out);
}

// round 3
// speedup vs baseline: 3.5053x; 3.5053x over previous
#include <cuda_runtime.h>
#include <cstdint>
#include <cstddef>

#define Bb 2
#define Ss 2048
#define Ee 1024
#define Hh 16
#define Dd 64
#define E3 3072

// Scratch (no allocations allowed anywhere)
__device__ float g_qkv[Bb * Ss * E3];   // [B,S,3E] = Q|K|V
__device__ float g_attn[Bb * Ss * Ee];  // [B,S,E]

// fp32 -> tf32 (round-to-nearest) as raw b32
__device__ __forceinline__ unsigned f2tf(float x) {
    unsigned u;
    asm("cvt.rna.tf32.f32 %0, %1;" : "=r"(u) : "f"(x));
    return u;
}

// D(16x8,f32) += A(16x8,tf32) * B(8x8,tf32)
__device__ __forceinline__ void mma_tf32(float* d, const unsigned* a, const unsigned* b) {
    asm("mma.sync.aligned.m16n8k8.row.col.f32.tf32.tf32.f32 "
        "{%0,%1,%2,%3}, {%4,%5,%6,%7}, {%8,%9}, {%0,%1,%2,%3};\n"
        : "+f"(d[0]), "+f"(d[1]), "+f"(d[2]), "+f"(d[3])
        : "r"(a[0]), "r"(a[1]), "r"(a[2]), "r"(a[3]),
          "r"(b[0]), "r"(b[1]));
}

// ---------------------------------------------------------------------------
// tf32 tensor-core GEMM: C = A[MxK] @ W[KxN] + bias
// Block: 256 thr (8 warps), tile 128x128, K-step 16, double-buffered SMEM.
// Warp w: 64x32 subtile at (64*(w&1), 32*(w>>1)); 4x4 m16n8k8 fragments.
// ---------------------------------------------------------------------------
#define GST 136   // SMEM row stride (floats): bank = (8k+m)%32, conflict-free

__device__ __forceinline__ void tgemm(
    const float* __restrict__ A, const float* __restrict__ W,
    const float* __restrict__ bias, float* __restrict__ C,
    int M, int N, int K)
{
    __shared__ unsigned As[2][16][GST];   // [k][m]
    __shared__ unsigned Bs[2][16][GST];   // [k][n]

    const int t = threadIdx.x;
    const int lane = t & 31, w = t >> 5;
    const int q = lane & 3, g = lane >> 2;
    const int m0 = (w & 1) * 64, n0 = (w >> 1) * 32;
    const int brow = blockIdx.y * 128, bcol = blockIdx.x * 128;

    const int arow = t & 127;            // A staging: row
    const int akq = (t >> 7) * 2;        // A staging: base float4-k index (0 or 2)

    const int nk = K / 16;

    float acc[4][4][4];
#pragma unroll
    for (int i = 0; i < 4; i++)
#pragma unroll
        for (int j = 0; j < 4; j++)
#pragma unroll
            for (int r = 0; r < 4; r++) acc[i][j][r] = 0.f;

    // Prologue: stage tile kt=0
    {
#pragma unroll
        for (int i = 0; i < 2; i++) {
            int kq = akq + i;
            float4 av = *(const float4*)(A + (size_t)(brow + arow) * K + kq * 4);
            As[0][kq * 4 + 0][arow] = f2tf(av.x);
            As[0][kq * 4 + 1][arow] = f2tf(av.y);
            As[0][kq * 4 + 2][arow] = f2tf(av.z);
            As[0][kq * 4 + 3][arow] = f2tf(av.w);
        }
#pragma unroll
        for (int i = 0; i < 2; i++) {
            int idx = t + i * 256;
            int kr = idx >> 5, c4 = idx & 31;
            float4 bv = *(const float4*)(W + (size_t)kr * N + bcol + c4 * 4);
            Bs[0][kr][c4 * 4 + 0] = f2tf(bv.x);
            Bs[0][kr][c4 * 4 + 1] = f2tf(bv.y);
            Bs[0][kr][c4 * 4 + 2] = f2tf(bv.z);
            Bs[0][kr][c4 * 4 + 3] = f2tf(bv.w);
        }
        __syncthreads();
    }

    for (int kt = 0; kt < nk; kt++) {
        const int cur = kt & 1;
        float4 avs[2], bvs[2];
        if (kt + 1 < nk) {
#pragma unroll
            for (int i = 0; i < 2; i++) {
                int kq = akq + i;
                avs[i] = *(const float4*)(A + (size_t)(brow + arow) * K +
                                          (kt + 1) * 16 + kq * 4);
            }
#pragma unroll
            for (int i = 0; i < 2; i++) {
                int idx = t + i * 256;
                int kr = idx >> 5, c4 = idx & 31;
                bvs[i] = *(const float4*)(W + (size_t)((kt + 1) * 16 + kr) * N +
                                          bcol + c4 * 4);
            }
        }

#pragma unroll
        for (int ks = 0; ks < 2; ks++) {
            const int kb = ks * 8;
            unsigned a[4][4], bfr[4][2];
#pragma unroll
            for (int mf = 0; mf < 4; mf++) {
                int mm = m0 + mf * 16 + g;
                a[mf][0] = As[cur][kb + q][mm];
                a[mf][1] = As[cur][kb + q][mm + 8];
                a[mf][2] = As[cur][kb + q + 4][mm];
                a[mf][3] = As[cur][kb + q + 4][mm + 8];
            }
#pragma unroll
            for (int nf = 0; nf < 4; nf++) {
                int nn = n0 + nf * 8 + g;
                bfr[nf][0] = Bs[cur][kb + q][nn];
                bfr[nf][1] = Bs[cur][kb + q + 4][nn];
            }
#pragma unroll
            for (int mf = 0; mf < 4; mf++)
#pragma unroll
                for (int nf = 0; nf < 4; nf++)
                    mma_tf32(acc[mf][nf], a[mf], bfr[nf]);
        }

        if (kt + 1 < nk) {
            const int nxt = cur ^ 1;
#pragma unroll
            for (int i = 0; i < 2; i++) {
                int kq = akq + i;
                As[nxt][kq * 4 + 0][arow] = f2tf(avs[i].x);
                As[nxt][kq * 4 + 1][arow] = f2tf(avs[i].y);
                As[nxt][kq * 4 + 2][arow] = f2tf(avs[i].z);
                As[nxt][kq * 4 + 3][arow] = f2tf(avs[i].w);
            }
#pragma unroll
            for (int i = 0; i < 2; i++) {
                int idx = t + i * 256;
                int kr = idx >> 5, c4 = idx & 31;
                Bs[nxt][kr][c4 * 4 + 0] = f2tf(bvs[i].x);
                Bs[nxt][kr][c4 * 4 + 1] = f2tf(bvs[i].y);
                Bs[nxt][kr][c4 * 4 + 2] = f2tf(bvs[i].z);
                Bs[nxt][kr][c4 * 4 + 3] = f2tf(bvs[i].w);
            }
            __syncthreads();
        }
    }

    // Epilogue: D layout c0:(r,2q) c1:(r,2q+1) c2:(r+8,2q) c3:(r+8,2q+1)
#pragma unroll
    for (int mf = 0; mf < 4; mf++) {
#pragma unroll
        for (int nf = 0; nf < 4; nf++) {
            int r0 = brow + m0 + mf * 16 + g;
            int c0 = bcol + n0 + nf * 8 + 2 * q;
            float bz0 = bias[c0], bz1 = bias[c0 + 1];
            *(float2*)(C + (size_t)r0 * N + c0) =
                make_float2(acc[mf][nf][0] + bz0, acc[mf][nf][1] + bz1);
            *(float2*)(C + (size_t)(r0 + 8) * N + c0) =
                make_float2(acc[mf][nf][2] + bz0, acc[mf][nf][3] + bz1);
        }
    }
}

__global__ __launch_bounds__(256) void qkv_gemm_kernel(
    const float* __restrict__ A, const float* __restrict__ W,
    const float* __restrict__ bias)
{
    tgemm(A, W, bias, g_qkv, Bb * Ss, E3, Ee);
}

__global__ __launch_bounds__(256) void proj_gemm_kernel(
    const float* __restrict__ W, const float* __restrict__ bias,
    float* __restrict__ C)
{
    tgemm(g_attn, W, bias, C, Bb * Ss, Ee, Ee);
}

// ---------------------------------------------------------------------------
// Flash attention with tf32 mma. Block: 128 thr (4 warps) = 64 queries;
// each warp owns 16 query rows. K/V tiles of 32 keys.
// S-columns are key-permuted (col 2q -> key q, col 2q+1 -> key q+4) so the
// QK C-fragment doubles as the PV A-fragment via register renaming.
// ---------------------------------------------------------------------------
#define QST 68
#define KST 68
#define VST 72

__global__ __launch_bounds__(128) void attn_mma_kernel()
{
    __shared__ unsigned Qs[64][QST];
    __shared__ unsigned Ks[32][KST];
    __shared__ unsigned Vs[32][VST];

    const int qt = blockIdx.x;            // 0..31 query tile
    const int bh = blockIdx.y;            // 0..31
    const int b = bh >> 4, h = bh & 15;
    const int t = threadIdx.x, lane = t & 31, w = t >> 5;
    const int q = lane & 3, g = lane >> 2;

    const float* base = g_qkv + (size_t)b * Ss * E3;

    // Stage Q (pre-scaled by 1/sqrt(D)=0.125), tf32
#pragma unroll
    for (int i = 0; i < 8; i++) {
        int idx = t + i * 128;            // 0..1023
        int r = idx >> 4, c4 = idx & 15;
        float4 v = *(const float4*)(base + (size_t)(qt * 64 + r) * E3 + h * 64 + c4 * 4);
        Qs[r][c4 * 4 + 0] = f2tf(v.x * 0.125f);
        Qs[r][c4 * 4 + 1] = f2tf(v.y * 0.125f);
        Qs[r][c4 * 4 + 2] = f2tf(v.z * 0.125f);
        Qs[r][c4 * 4 + 3] = f2tf(v.w * 0.125f);
    }
    __syncthreads();

    // Q A-fragments into registers: 8 k-steps x 4 regs
    unsigned aq[8][4];
#pragma unroll
    for (int kk = 0; kk < 8; kk++) {
        aq[kk][0] = Qs[w * 16 + g][kk * 8 + q];
        aq[kk][1] = Qs[w * 16 + g + 8][kk * 8 + q];
        aq[kk][2] = Qs[w * 16 + g][kk * 8 + q + 4];
        aq[kk][3] = Qs[w * 16 + g + 8][kk * 8 + q + 4];
    }

    float m0r = -1e30f, m1r = -1e30f, l0 = 0.f, l1 = 0.f;
    float o[8][4];
#pragma unroll
    for (int nf = 0; nf < 8; nf++)
#pragma unroll
        for (int r = 0; r < 4; r++) o[nf][r] = 0.f;

    const int r0 = qt * 64 + w * 16;                 // warp's first query row
    const int myTiles = (r0 + 15) / 32 + 1;          // tiles this warp computes
    const int nkt = 2 * qt + 2;                      // tiles the block stages
    const int pg = (g >> 1) | ((g & 1) << 2);        // permuted key-in-frag

    for (int kt = 0; kt < nkt; kt++) {
        __syncthreads();
#pragma unroll
        for (int i = 0; i < 4; i++) {
            int idx = t + i * 128;        // 0..511
            int r = idx >> 4, c4 = idx & 15;
            const float* kp = base + (size_t)(kt * 32 + r) * E3 + Ee + h * 64 + c4 * 4;
            float4 kv = *(const float4*)kp;
            float4 vv = *(const float4*)(kp + Ee);
            Ks[r][c4 * 4 + 0] = f2tf(kv.x);
            Ks[r][c4 * 4 + 1] = f2tf(kv.y);
            Ks[r][c4 * 4 + 2] = f2tf(kv.z);
            Ks[r][c4 * 4 + 3] = f2tf(kv.w);
            Vs[r][c4 * 4 + 0] = f2tf(vv.x);
            Vs[r][c4 * 4 + 1] = f2tf(vv.y);
            Vs[r][c4 * 4 + 2] = f2tf(vv.z);
            Vs[r][c4 * 4 + 3] = f2tf(vv.w);
        }
        __syncthreads();

        if (kt >= myTiles) continue;      // warp-uniform; all syncs still hit

        // S = Q @ K^T with permuted columns
        float s[4][4];
#pragma unroll
        for (int nf = 0; nf < 4; nf++)
#pragma unroll
            for (int r = 0; r < 4; r++) s[nf][r] = 0.f;

#pragma unroll
        for (int kk = 0; kk < 8; kk++) {
#pragma unroll
            for (int nf = 0; nf < 4; nf++) {
                unsigned bb[2];
                bb[0] = Ks[nf * 8 + pg][kk * 8 + q];
                bb[1] = Ks[nf * 8 + pg][kk * 8 + q + 4];
                mma_tf32(s[nf], aq[kk], bb);
            }
        }

        // Causal mask, only on this warp's last tile
        if (kt == myTiles - 1) {
            const int row0 = r0 + g;
#pragma unroll
            for (int nf = 0; nf < 4; nf++) {
                int k0 = kt * 32 + nf * 8 + q;  // key for regs 0,2
                int k1 = k0 + 4;                // key for regs 1,3
                if (k0 > row0)     s[nf][0] = -1e30f;
                if (k1 > row0)     s[nf][1] = -1e30f;
                if (k0 > row0 + 8) s[nf][2] = -1e30f;
                if (k1 > row0 + 8) s[nf][3] = -1e30f;
            }
        }

        // Online softmax (each thread owns rows row0 and row0+8)
        float t0 = -1e30f, t1 = -1e30f;
#pragma unroll
        for (int nf = 0; nf < 4; nf++) {
            t0 = fmaxf(t0, fmaxf(s[nf][0], s[nf][1]));
            t1 = fmaxf(t1, fmaxf(s[nf][2], s[nf][3]));
        }
        t0 = fmaxf(t0, __shfl_xor_sync(0xffffffffu, t0, 1));
        t0 = fmaxf(t0, __shfl_xor_sync(0xffffffffu, t0, 2));
        t1 = fmaxf(t1, __shfl_xor_sync(0xffffffffu, t1, 1));
        t1 = fmaxf(t1, __shfl_xor_sync(0xffffffffu, t1, 2));

        float nm0 = fmaxf(m0r, t0), nm1 = fmaxf(m1r, t1);
        float cr0 = __expf(m0r - nm0), cr1 = __expf(m1r - nm1);
        m0r = nm0; m1r = nm1;
        l0 *= cr0; l1 *= cr1;
#pragma unroll
        for (int nf = 0; nf < 8; nf++) {
            o[nf][0] *= cr0; o[nf][1] *= cr0;
            o[nf][2] *= cr1; o[nf][3] *= cr1;
        }

        // P = exp(S - m); repack C-frag {c0,c2,c1,c3} as A-frag, tf32
        unsigned p[4][4];
#pragma unroll
        for (int nf = 0; nf < 4; nf++) {
            float e0 = __expf(s[nf][0] - nm0);
            float e1 = __expf(s[nf][1] - nm0);
            float e2 = __expf(s[nf][2] - nm1);
            float e3 = __expf(s[nf][3] - nm1);
            l0 += e0 + e1;
            l1 += e2 + e3;
            p[nf][0] = f2tf(e0);
            p[nf][1] = f2tf(e2);
            p[nf][2] = f2tf(e1);
            p[nf][3] = f2tf(e3);
        }

        // O += P @ V
#pragma unroll
        for (int kk = 0; kk < 4; kk++) {
#pragma unroll
            for (int nf = 0; nf < 8; nf++) {
                unsigned bb[2];
                bb[0] = Vs[kk * 8 + q][nf * 8 + g];
                bb[1] = Vs[kk * 8 + q + 4][nf * 8 + g];
                mma_tf32(o[nf], p[kk], bb);
            }
        }
    }

    // Final l reduce across the 4-lane row group
    l0 += __shfl_xor_sync(0xffffffffu, l0, 1);
    l0 += __shfl_xor_sync(0xffffffffu, l0, 2);
    l1 += __shfl_xor_sync(0xffffffffu, l1, 1);
    l1 += __shfl_xor_sync(0xffffffffu, l1, 2);
    const float i0 = 1.f / l0, i1 = 1.f / l1;

    float* orow0 = g_attn + ((size_t)b * Ss + r0 + g) * Ee + h * 64;
    float* orow1 = g_attn + ((size_t)b * Ss + r0 + g + 8) * Ee + h * 64;
#pragma unroll
    for (int nf = 0; nf < 8; nf++) {
        int c = nf * 8 + 2 * q;
        *(float2*)(orow0 + c) = make_float2(o[nf][0] * i0, o[nf][1] * i0);
        *(float2*)(orow1 + c) = make_float2(o[nf][2] * i1, o[nf][3] * i1);
    }
}

// ---------------------------------------------------------------------------
extern "C" void kernel_launch(void* const* d_in, const int* in_sizes, int n_in,
                              void* d_out, int out_size)
{
    const float* hs    = (const float*)d_in[0];
    const float* wqkv  = (const float*)d_in[1];
    const float* bqkv  = (const float*)d_in[2];
    const float* wproj = (const float*)d_in[3];
    const float* bproj = (const float*)d_in[4];
    float* out = (float*)d_out;

    dim3 g1(E3 / 128, (Bb * Ss) / 128);   // 24 x 32
    qkv_gemm_kernel<<<g1, 256>>>(hs, wqkv, bqkv);

    dim3 g2(Ss / 64, Bb * Hh);            // 32 x 32
    attn_mma_kernel<<<g2, 128>>>();

    dim3 g3(Ee / 128, (Bb * Ss) / 128);   // 8 x 32
    proj_gemm_kernel<<<g3, 256>>>(wproj, bproj, out);
}

// round 5
// speedup vs baseline: 4.6389x; 1.3234x over previous
#include <cuda_runtime.h>
#include <cstdint>
#include <cstddef>

#define Bb 2
#define Ss 2048
#define Ee 1024
#define Hh 16
#define Dd 64
#define E3 3072

// Scratch (no allocations allowed anywhere)
__device__ float g_qkv[Bb * Ss * E3];   // [B,S,3E] = Q|K|V
__device__ float g_attn[Bb * Ss * Ee];  // [B,S,E]

// fp32 -> tf32 (round-to-nearest) as raw b32
__device__ __forceinline__ unsigned f2tf(float x) {
    unsigned u;
    asm("cvt.rna.tf32.f32 %0, %1;" : "=r"(u) : "f"(x));
    return u;
}

// D(16x8,f32) += A(16x8,tf32) * B(8x8,tf32)
__device__ __forceinline__ void mma_tf32(float* d, const unsigned* a, const unsigned* b) {
    asm("mma.sync.aligned.m16n8k8.row.col.f32.tf32.tf32.f32 "
        "{%0,%1,%2,%3}, {%4,%5,%6,%7}, {%8,%9}, {%0,%1,%2,%3};\n"
        : "+f"(d[0]), "+f"(d[1]), "+f"(d[2]), "+f"(d[3])
        : "r"(a[0]), "r"(a[1]), "r"(a[2]), "r"(a[3]),
          "r"(b[0]), "r"(b[1]));
}

__device__ __forceinline__ void cpa16(void* dst, const void* src) {
    unsigned s = (unsigned)__cvta_generic_to_shared(dst);
    asm volatile("cp.async.cg.shared.global [%0], [%1], 16;" :: "r"(s), "l"(src));
}
__device__ __forceinline__ void cpa_commit() {
    asm volatile("cp.async.commit_group;");
}
__device__ __forceinline__ void cpa_wait1() {
    asm volatile("cp.async.wait_group 1;");
}

// ---------------------------------------------------------------------------
// tf32 GEMM: C = A[MxK] @ W[KxN] + bias
// Block 256 thr (8 warps), tile 128x256, K-step 16, 3-stage cp.async pipeline.
// Warp w: 64x64 subtile at (64*(w&1), 64*(w>>1)); 4x8 m16n8k8 fragments.
// SMEM per stage: A[128][20] (pad->conflict-free), B[16][264].
// ---------------------------------------------------------------------------
#define ASTR 20
#define BSTR 264
#define ASZ  (128 * ASTR)          // 2560 floats
#define BSZ  (16 * BSTR)           // 4224 floats
#define STG  (ASZ + BSZ)           // 6784 floats per stage
#define SMEM_BYTES (3 * STG * 4)   // 81408 B

__device__ __forceinline__ void tgemm2(
    const float* __restrict__ A, const float* __restrict__ W,
    const float* __restrict__ bias, float* __restrict__ C,
    int N, int K)
{
    extern __shared__ float sh[];

    const int t = threadIdx.x;
    const int lane = t & 31, w = t >> 5;
    const int q = lane & 3, g = lane >> 2;
    const int wm = (w & 1) * 64, wn = (w >> 1) * 64;
    const int brow = blockIdx.y * 128, bcol = blockIdx.x * 256;
    const int nk = K / 16;

    float acc[4][8][4];
#pragma unroll
    for (int i = 0; i < 4; i++)
#pragma unroll
        for (int j = 0; j < 8; j++)
#pragma unroll
            for (int r = 0; r < 4; r++) acc[i][j][r] = 0.f;

    // ---- stage issuance: 2 A-chunks + 4 B-chunks per thread ----
    auto stage = [&](int st, int kt) {
        float* As = sh + st * STG;
        float* Bs = As + ASZ;
#pragma unroll
        for (int i = 0; i < 2; i++) {
            int c = t + i * 256;          // 0..511
            int m = c >> 2, k4 = c & 3;
            cpa16(As + m * ASTR + k4 * 4,
                  A + (size_t)(brow + m) * K + kt * 16 + k4 * 4);
        }
#pragma unroll
        for (int i = 0; i < 4; i++) {
            int c = t + i * 256;          // 0..1023
            int k = c >> 6, n4 = c & 63;
            cpa16(Bs + k * BSTR + n4 * 4,
                  W + (size_t)(kt * 16 + k) * N + bcol + n4 * 4);
        }
    };

    stage(0, 0); cpa_commit();
    stage(1, 1); cpa_commit();

    for (int kt = 0; kt < nk; kt++) {
        cpa_wait1();
        __syncthreads();
        if (kt + 2 < nk) stage((kt + 2) % 3, kt + 2);
        cpa_commit();

        const float* As = sh + (kt % 3) * STG;
        const float* Bs = As + ASZ;

#pragma unroll
        for (int ks = 0; ks < 2; ks++) {
            unsigned af[4][4], bf[8][2];
#pragma unroll
            for (int mf = 0; mf < 4; mf++) {
                const float* p  = As + (wm + mf * 16 + g) * ASTR + ks * 8;
                const float* p8 = p + 8 * ASTR;
                af[mf][0] = f2tf(p[q]);
                af[mf][1] = f2tf(p8[q]);
                af[mf][2] = f2tf(p[q + 4]);
                af[mf][3] = f2tf(p8[q + 4]);
            }
#pragma unroll
            for (int nf = 0; nf < 8; nf++) {
                const int n = wn + nf * 8 + g;
                bf[nf][0] = f2tf(Bs[(ks * 8 + q) * BSTR + n]);
                bf[nf][1] = f2tf(Bs[(ks * 8 + q + 4) * BSTR + n]);
            }
#pragma unroll
            for (int mf = 0; mf < 4; mf++)
#pragma unroll
                for (int nf = 0; nf < 8; nf++)
                    mma_tf32(acc[mf][nf], af[mf], bf[nf]);
        }
    }

    // Epilogue: c0:(r,2q) c1:(r,2q+1) c2:(r+8,2q) c3:(r+8,2q+1)
#pragma unroll
    for (int mf = 0; mf < 4; mf++) {
#pragma unroll
        for (int nf = 0; nf < 8; nf++) {
            int r0 = brow + wm + mf * 16 + g;
            int c0 = bcol + wn + nf * 8 + 2 * q;
            float bz0 = bias[c0], bz1 = bias[c0 + 1];
            *(float2*)(C + (size_t)r0 * N + c0) =
                make_float2(acc[mf][nf][0] + bz0, acc[mf][nf][1] + bz1);
            *(float2*)(C + (size_t)(r0 + 8) * N + c0) =
                make_float2(acc[mf][nf][2] + bz0, acc[mf][nf][3] + bz1);
        }
    }
}

__global__ __launch_bounds__(256, 1) void qkv_gemm_kernel(
    const float* __restrict__ A, const float* __restrict__ W,
    const float* __restrict__ bias)
{
    tgemm2(A, W, bias, g_qkv, E3, Ee);
}

__global__ __launch_bounds__(256, 1) void proj_gemm_kernel(
    const float* __restrict__ W, const float* __restrict__ bias,
    float* __restrict__ C)
{
    tgemm2(g_attn, W, bias, C, Ee, Ee);
}

// ---------------------------------------------------------------------------
// Flash attention with tf32 mma (unchanged from round 2 — verified correct).
// ---------------------------------------------------------------------------
#define QST 68
#define KST 68
#define VST 72

__global__ __launch_bounds__(128) void attn_mma_kernel()
{
    __shared__ unsigned Qs[64][QST];
    __shared__ unsigned Ks[32][KST];
    __shared__ unsigned Vs[32][VST];

    const int qt = blockIdx.x;
    const int bh = blockIdx.y;
    const int b = bh >> 4, h = bh & 15;
    const int t = threadIdx.x, lane = t & 31, w = t >> 5;
    const int q = lane & 3, g = lane >> 2;

    const float* base = g_qkv + (size_t)b * Ss * E3;

#pragma unroll
    for (int i = 0; i < 8; i++) {
        int idx = t + i * 128;
        int r = idx >> 4, c4 = idx & 15;
        float4 v = *(const float4*)(base + (size_t)(qt * 64 + r) * E3 + h * 64 + c4 * 4);
        Qs[r][c4 * 4 + 0] = f2tf(v.x * 0.125f);
        Qs[r][c4 * 4 + 1] = f2tf(v.y * 0.125f);
        Qs[r][c4 * 4 + 2] = f2tf(v.z * 0.125f);
        Qs[r][c4 * 4 + 3] = f2tf(v.w * 0.125f);
    }
    __syncthreads();

    unsigned aq[8][4];
#pragma unroll
    for (int kk = 0; kk < 8; kk++) {
        aq[kk][0] = Qs[w * 16 + g][kk * 8 + q];
        aq[kk][1] = Qs[w * 16 + g + 8][kk * 8 + q];
        aq[kk][2] = Qs[w * 16 + g][kk * 8 + q + 4];
        aq[kk][3] = Qs[w * 16 + g + 8][kk * 8 + q + 4];
    }

    float m0r = -1e30f, m1r = -1e30f, l0 = 0.f, l1 = 0.f;
    float o[8][4];
#pragma unroll
    for (int nf = 0; nf < 8; nf++)
#pragma unroll
        for (int r = 0; r < 4; r++) o[nf][r] = 0.f;

    const int r0 = qt * 64 + w * 16;
    const int myTiles = (r0 + 15) / 32 + 1;
    const int nkt = 2 * qt + 2;
    const int pg = (g >> 1) | ((g & 1) << 2);

    for (int kt = 0; kt < nkt; kt++) {
        __syncthreads();
#pragma unroll
        for (int i = 0; i < 4; i++) {
            int idx = t + i * 128;
            int r = idx >> 4, c4 = idx & 15;
            const float* kp = base + (size_t)(kt * 32 + r) * E3 + Ee + h * 64 + c4 * 4;
            float4 kv = *(const float4*)kp;
            float4 vv = *(const float4*)(kp + Ee);
            Ks[r][c4 * 4 + 0] = f2tf(kv.x);
            Ks[r][c4 * 4 + 1] = f2tf(kv.y);
            Ks[r][c4 * 4 + 2] = f2tf(kv.z);
            Ks[r][c4 * 4 + 3] = f2tf(kv.w);
            Vs[r][c4 * 4 + 0] = f2tf(vv.x);
            Vs[r][c4 * 4 + 1] = f2tf(vv.y);
            Vs[r][c4 * 4 + 2] = f2tf(vv.z);
            Vs[r][c4 * 4 + 3] = f2tf(vv.w);
        }
        __syncthreads();

        if (kt >= myTiles) continue;

        float s[4][4];
#pragma unroll
        for (int nf = 0; nf < 4; nf++)
#pragma unroll
            for (int r = 0; r < 4; r++) s[nf][r] = 0.f;

#pragma unroll
        for (int kk = 0; kk < 8; kk++) {
#pragma unroll
            for (int nf = 0; nf < 4; nf++) {
                unsigned bb[2];
                bb[0] = Ks[nf * 8 + pg][kk * 8 + q];
                bb[1] = Ks[nf * 8 + pg][kk * 8 + q + 4];
                mma_tf32(s[nf], aq[kk], bb);
            }
        }

        if (kt == myTiles - 1) {
            const int row0 = r0 + g;
#pragma unroll
            for (int nf = 0; nf < 4; nf++) {
                int k0 = kt * 32 + nf * 8 + q;
                int k1 = k0 + 4;
                if (k0 > row0)     s[nf][0] = -1e30f;
                if (k1 > row0)     s[nf][1] = -1e30f;
                if (k0 > row0 + 8) s[nf][2] = -1e30f;
                if (k1 > row0 + 8) s[nf][3] = -1e30f;
            }
        }

        float t0 = -1e30f, t1 = -1e30f;
#pragma unroll
        for (int nf = 0; nf < 4; nf++) {
            t0 = fmaxf(t0, fmaxf(s[nf][0], s[nf][1]));
            t1 = fmaxf(t1, fmaxf(s[nf][2], s[nf][3]));
        }
        t0 = fmaxf(t0, __shfl_xor_sync(0xffffffffu, t0, 1));
        t0 = fmaxf(t0, __shfl_xor_sync(0xffffffffu, t0, 2));
        t1 = fmaxf(t1, __shfl_xor_sync(0xffffffffu, t1, 1));
        t1 = fmaxf(t1, __shfl_xor_sync(0xffffffffu, t1, 2));

        float nm0 = fmaxf(m0r, t0), nm1 = fmaxf(m1r, t1);
        float cr0 = __expf(m0r - nm0), cr1 = __expf(m1r - nm1);
        m0r = nm0; m1r = nm1;
        l0 *= cr0; l1 *= cr1;
#pragma unroll
        for (int nf = 0; nf < 8; nf++) {
            o[nf][0] *= cr0; o[nf][1] *= cr0;
            o[nf][2] *= cr1; o[nf][3] *= cr1;
        }

        unsigned p[4][4];
#pragma unroll
        for (int nf = 0; nf < 4; nf++) {
            float e0 = __expf(s[nf][0] - nm0);
            float e1 = __expf(s[nf][1] - nm0);
            float e2 = __expf(s[nf][2] - nm1);
            float e3 = __expf(s[nf][3] - nm1);
            l0 += e0 + e1;
            l1 += e2 + e3;
            p[nf][0] = f2tf(e0);
            p[nf][1] = f2tf(e2);
            p[nf][2] = f2tf(e1);
            p[nf][3] = f2tf(e3);
        }

#pragma unroll
        for (int kk = 0; kk < 4; kk++) {
#pragma unroll
            for (int nf = 0; nf < 8; nf++) {
                unsigned bb[2];
                bb[0] = Vs[kk * 8 + q][nf * 8 + g];
                bb[1] = Vs[kk * 8 + q + 4][nf * 8 + g];
                mma_tf32(o[nf], p[kk], bb);
            }
        }
    }

    l0 += __shfl_xor_sync(0xffffffffu, l0, 1);
    l0 += __shfl_xor_sync(0xffffffffu, l0, 2);
    l1 += __shfl_xor_sync(0xffffffffu, l1, 1);
    l1 += __shfl_xor_sync(0xffffffffu, l1, 2);
    const float i0 = 1.f / l0, i1 = 1.f / l1;

    float* orow0 = g_attn + ((size_t)b * Ss + r0 + g) * Ee + h * 64;
    float* orow1 = g_attn + ((size_t)b * Ss + r0 + g + 8) * Ee + h * 64;
#pragma unroll
    for (int nf = 0; nf < 8; nf++) {
        int c = nf * 8 + 2 * q;
        *(float2*)(orow0 + c) = make_float2(o[nf][0] * i0, o[nf][1] * i0);
        *(float2*)(orow1 + c) = make_float2(o[nf][2] * i1, o[nf][3] * i1);
    }
}

// ---------------------------------------------------------------------------
extern "C" void kernel_launch(void* const* d_in, const int* in_sizes, int n_in,
                              void* d_out, int out_size)
{
    const float* hs    = (const float*)d_in[0];
    const float* wqkv  = (const float*)d_in[1];
    const float* bqkv  = (const float*)d_in[2];
    const float* wproj = (const float*)d_in[3];
    const float* bproj = (const float*)d_in[4];
    float* out = (float*)d_out;

    static int smem_set = 0;
    if (!smem_set) {
        cudaFuncSetAttribute(qkv_gemm_kernel,
                             cudaFuncAttributeMaxDynamicSharedMemorySize, SMEM_BYTES);
        cudaFuncSetAttribute(proj_gemm_kernel,
                             cudaFuncAttributeMaxDynamicSharedMemorySize, SMEM_BYTES);
        smem_set = 1;
    }

    dim3 g1(E3 / 256, (Bb * Ss) / 128);   // 12 x 32
    qkv_gemm_kernel<<<g1, 256, SMEM_BYTES>>>(hs, wqkv, bqkv);

    dim3 g2(Ss / 64, Bb * Hh);            // 32 x 32
    attn_mma_kernel<<<g2, 128>>>();

    dim3 g3(Ee / 256, (Bb * Ss) / 128);   // 4 x 32
    proj_gemm_kernel<<<g3, 256, SMEM_BYTES>>>(wproj, bproj, out);
}

// round 6
// speedup vs baseline: 4.8916x; 1.0545x over previous
#include <cuda_runtime.h>
#include <cstdint>
#include <cstddef>

#define Bb 2
#define Ss 2048
#define Ee 1024
#define Hh 16
#define Dd 64
#define E3 3072

// Scratch (no allocations allowed anywhere)
__device__ float g_qkv[Bb * Ss * E3];   // [B,S,3E] = Q|K|V
__device__ float g_attn[Bb * Ss * Ee];  // [B,S,E]

// fp32 -> tf32 (round-to-nearest) as raw b32
__device__ __forceinline__ unsigned f2tf(float x) {
    unsigned u;
    asm("cvt.rna.tf32.f32 %0, %1;" : "=r"(u) : "f"(x));
    return u;
}

// D(16x8,f32) += A(16x8,tf32) * B(8x8,tf32)
__device__ __forceinline__ void mma_tf32(float* d, const unsigned* a, const unsigned* b) {
    asm("mma.sync.aligned.m16n8k8.row.col.f32.tf32.tf32.f32 "
        "{%0,%1,%2,%3}, {%4,%5,%6,%7}, {%8,%9}, {%0,%1,%2,%3};\n"
        : "+f"(d[0]), "+f"(d[1]), "+f"(d[2]), "+f"(d[3])
        : "r"(a[0]), "r"(a[1]), "r"(a[2]), "r"(a[3]),
          "r"(b[0]), "r"(b[1]));
}

__device__ __forceinline__ void cpa16(void* dst, const void* src) {
    unsigned s = (unsigned)__cvta_generic_to_shared(dst);
    asm volatile("cp.async.cg.shared.global [%0], [%1], 16;" :: "r"(s), "l"(src));
}
__device__ __forceinline__ void cpa_commit() {
    asm volatile("cp.async.commit_group;");
}
__device__ __forceinline__ void cpa_wait1() {
    asm volatile("cp.async.wait_group 1;");
}

// ---------------------------------------------------------------------------
// tf32 GEMM: C = A[MxK] @ W[KxN] + bias
// Block 256 thr (8 warps), tile 128x128, K-step 16, 3-stage cp.async pipeline,
// sized for 2 CTAs/SM (regs <= 128 via __launch_bounds__, smem 56.8KB/CTA).
// Warp w: 64x32 subtile at (64*(w&1), 32*(w>>1)); 4x4 m16n8k8 fragments.
// ---------------------------------------------------------------------------
#define ASTR 20
#define BSTR 136
#define ASZ  (128 * ASTR)          // 2560 floats
#define BSZ  (16 * BSTR)           // 2176 floats
#define STG  (ASZ + BSZ)           // 4736 floats per stage
#define SMEM_BYTES (3 * STG * 4)   // 56832 B

__device__ __forceinline__ void tgemm2(
    const float* __restrict__ A, const float* __restrict__ W,
    const float* __restrict__ bias, float* __restrict__ C,
    int N, int K)
{
    extern __shared__ float sh[];

    const int t = threadIdx.x;
    const int lane = t & 31, w = t >> 5;
    const int q = lane & 3, g = lane >> 2;
    const int wm = (w & 1) * 64, wn = (w >> 1) * 32;
    const int brow = blockIdx.y * 128, bcol = blockIdx.x * 128;
    const int nk = K / 16;

    float acc[4][4][4];
#pragma unroll
    for (int i = 0; i < 4; i++)
#pragma unroll
        for (int j = 0; j < 4; j++)
#pragma unroll
            for (int r = 0; r < 4; r++) acc[i][j][r] = 0.f;

    // ---- stage issuance: 2 A-chunks + 2 B-chunks per thread ----
    auto stage = [&](int st, int kt) {
        float* As = sh + st * STG;
        float* Bs = As + ASZ;
#pragma unroll
        for (int i = 0; i < 2; i++) {
            int c = t + i * 256;          // 0..511
            int m = c >> 2, k4 = c & 3;
            cpa16(As + m * ASTR + k4 * 4,
                  A + (size_t)(brow + m) * K + kt * 16 + k4 * 4);
        }
#pragma unroll
        for (int i = 0; i < 2; i++) {
            int c = t + i * 256;          // 0..511
            int k = c >> 5, n4 = c & 31;
            cpa16(Bs + k * BSTR + n4 * 4,
                  W + (size_t)(kt * 16 + k) * N + bcol + n4 * 4);
        }
    };

    stage(0, 0); cpa_commit();
    stage(1, 1); cpa_commit();

    for (int kt = 0; kt < nk; kt++) {
        cpa_wait1();
        __syncthreads();
        if (kt + 2 < nk) stage((kt + 2) % 3, kt + 2);
        cpa_commit();

        const float* As = sh + (kt % 3) * STG;
        const float* Bs = As + ASZ;

#pragma unroll
        for (int ks = 0; ks < 2; ks++) {
            unsigned af[4][4], bf[4][2];
#pragma unroll
            for (int mf = 0; mf < 4; mf++) {
                const float* p  = As + (wm + mf * 16 + g) * ASTR + ks * 8;
                const float* p8 = p + 8 * ASTR;
                af[mf][0] = f2tf(p[q]);
                af[mf][1] = f2tf(p8[q]);
                af[mf][2] = f2tf(p[q + 4]);
                af[mf][3] = f2tf(p8[q + 4]);
            }
#pragma unroll
            for (int nf = 0; nf < 4; nf++) {
                const int n = wn + nf * 8 + g;
                bf[nf][0] = f2tf(Bs[(ks * 8 + q) * BSTR + n]);
                bf[nf][1] = f2tf(Bs[(ks * 8 + q + 4) * BSTR + n]);
            }
#pragma unroll
            for (int mf = 0; mf < 4; mf++)
#pragma unroll
                for (int nf = 0; nf < 4; nf++)
                    mma_tf32(acc[mf][nf], af[mf], bf[nf]);
        }
    }

    // Epilogue: c0:(r,2q) c1:(r,2q+1) c2:(r+8,2q) c3:(r+8,2q+1)
#pragma unroll
    for (int mf = 0; mf < 4; mf++) {
#pragma unroll
        for (int nf = 0; nf < 4; nf++) {
            int r0 = brow + wm + mf * 16 + g;
            int c0 = bcol + wn + nf * 8 + 2 * q;
            float bz0 = bias[c0], bz1 = bias[c0 + 1];
            *(float2*)(C + (size_t)r0 * N + c0) =
                make_float2(acc[mf][nf][0] + bz0, acc[mf][nf][1] + bz1);
            *(float2*)(C + (size_t)(r0 + 8) * N + c0) =
                make_float2(acc[mf][nf][2] + bz0, acc[mf][nf][3] + bz1);
        }
    }
}

__global__ __launch_bounds__(256, 2) void qkv_gemm_kernel(
    const float* __restrict__ A, const float* __restrict__ W,
    const float* __restrict__ bias)
{
    tgemm2(A, W, bias, g_qkv, E3, Ee);
}

__global__ __launch_bounds__(256, 2) void proj_gemm_kernel(
    const float* __restrict__ W, const float* __restrict__ bias,
    float* __restrict__ C)
{
    tgemm2(g_attn, W, bias, C, Ee, Ee);
}

// ---------------------------------------------------------------------------
// Flash attention with tf32 mma (unchanged — verified correct).
// ---------------------------------------------------------------------------
#define QST 68
#define KST 68
#define VST 72

__global__ __launch_bounds__(128) void attn_mma_kernel()
{
    __shared__ unsigned Qs[64][QST];
    __shared__ unsigned Ks[32][KST];
    __shared__ unsigned Vs[32][VST];

    const int qt = blockIdx.x;
    const int bh = blockIdx.y;
    const int b = bh >> 4, h = bh & 15;
    const int t = threadIdx.x, lane = t & 31, w = t >> 5;
    const int q = lane & 3, g = lane >> 2;

    const float* base = g_qkv + (size_t)b * Ss * E3;

#pragma unroll
    for (int i = 0; i < 8; i++) {
        int idx = t + i * 128;
        int r = idx >> 4, c4 = idx & 15;
        float4 v = *(const float4*)(base + (size_t)(qt * 64 + r) * E3 + h * 64 + c4 * 4);
        Qs[r][c4 * 4 + 0] = f2tf(v.x * 0.125f);
        Qs[r][c4 * 4 + 1] = f2tf(v.y * 0.125f);
        Qs[r][c4 * 4 + 2] = f2tf(v.z * 0.125f);
        Qs[r][c4 * 4 + 3] = f2tf(v.w * 0.125f);
    }
    __syncthreads();

    unsigned aq[8][4];
#pragma unroll
    for (int kk = 0; kk < 8; kk++) {
        aq[kk][0] = Qs[w * 16 + g][kk * 8 + q];
        aq[kk][1] = Qs[w * 16 + g + 8][kk * 8 + q];
        aq[kk][2] = Qs[w * 16 + g][kk * 8 + q + 4];
        aq[kk][3] = Qs[w * 16 + g + 8][kk * 8 + q + 4];
    }

    float m0r = -1e30f, m1r = -1e30f, l0 = 0.f, l1 = 0.f;
    float o[8][4];
#pragma unroll
    for (int nf = 0; nf < 8; nf++)
#pragma unroll
        for (int r = 0; r < 4; r++) o[nf][r] = 0.f;

    const int r0 = qt * 64 + w * 16;
    const int myTiles = (r0 + 15) / 32 + 1;
    const int nkt = 2 * qt + 2;
    const int pg = (g >> 1) | ((g & 1) << 2);

    for (int kt = 0; kt < nkt; kt++) {
        __syncthreads();
#pragma unroll
        for (int i = 0; i < 4; i++) {
            int idx = t + i * 128;
            int r = idx >> 4, c4 = idx & 15;
            const float* kp = base + (size_t)(kt * 32 + r) * E3 + Ee + h * 64 + c4 * 4;
            float4 kv = *(const float4*)kp;
            float4 vv = *(const float4*)(kp + Ee);
            Ks[r][c4 * 4 + 0] = f2tf(kv.x);
            Ks[r][c4 * 4 + 1] = f2tf(kv.y);
            Ks[r][c4 * 4 + 2] = f2tf(kv.z);
            Ks[r][c4 * 4 + 3] = f2tf(kv.w);
            Vs[r][c4 * 4 + 0] = f2tf(vv.x);
            Vs[r][c4 * 4 + 1] = f2tf(vv.y);
            Vs[r][c4 * 4 + 2] = f2tf(vv.z);
            Vs[r][c4 * 4 + 3] = f2tf(vv.w);
        }
        __syncthreads();

        if (kt >= myTiles) continue;

        float s[4][4];
#pragma unroll
        for (int nf = 0; nf < 4; nf++)
#pragma unroll
            for (int r = 0; r < 4; r++) s[nf][r] = 0.f;

#pragma unroll
        for (int kk = 0; kk < 8; kk++) {
#pragma unroll
            for (int nf = 0; nf < 4; nf++) {
                unsigned bb[2];
                bb[0] = Ks[nf * 8 + pg][kk * 8 + q];
                bb[1] = Ks[nf * 8 + pg][kk * 8 + q + 4];
                mma_tf32(s[nf], aq[kk], bb);
            }
        }

        if (kt == myTiles - 1) {
            const int row0 = r0 + g;
#pragma unroll
            for (int nf = 0; nf < 4; nf++) {
                int k0 = kt * 32 + nf * 8 + q;
                int k1 = k0 + 4;
                if (k0 > row0)     s[nf][0] = -1e30f;
                if (k1 > row0)     s[nf][1] = -1e30f;
                if (k0 > row0 + 8) s[nf][2] = -1e30f;
                if (k1 > row0 + 8) s[nf][3] = -1e30f;
            }
        }

        float t0 = -1e30f, t1 = -1e30f;
#pragma unroll
        for (int nf = 0; nf < 4; nf++) {
            t0 = fmaxf(t0, fmaxf(s[nf][0], s[nf][1]));
            t1 = fmaxf(t1, fmaxf(s[nf][2], s[nf][3]));
        }
        t0 = fmaxf(t0, __shfl_xor_sync(0xffffffffu, t0, 1));
        t0 = fmaxf(t0, __shfl_xor_sync(0xffffffffu, t0, 2));
        t1 = fmaxf(t1, __shfl_xor_sync(0xffffffffu, t1, 1));
        t1 = fmaxf(t1, __shfl_xor_sync(0xffffffffu, t1, 2));

        float nm0 = fmaxf(m0r, t0), nm1 = fmaxf(m1r, t1);
        float cr0 = __expf(m0r - nm0), cr1 = __expf(m1r - nm1);
        m0r = nm0; m1r = nm1;
        l0 *= cr0; l1 *= cr1;
#pragma unroll
        for (int nf = 0; nf < 8; nf++) {
            o[nf][0] *= cr0; o[nf][1] *= cr0;
            o[nf][2] *= cr1; o[nf][3] *= cr1;
        }

        unsigned p[4][4];
#pragma unroll
        for (int nf = 0; nf < 4; nf++) {
            float e0 = __expf(s[nf][0] - nm0);
            float e1 = __expf(s[nf][1] - nm0);
            float e2 = __expf(s[nf][2] - nm1);
            float e3 = __expf(s[nf][3] - nm1);
            l0 += e0 + e1;
            l1 += e2 + e3;
            p[nf][0] = f2tf(e0);
            p[nf][1] = f2tf(e2);
            p[nf][2] = f2tf(e1);
            p[nf][3] = f2tf(e3);
        }

#pragma unroll
        for (int kk = 0; kk < 4; kk++) {
#pragma unroll
            for (int nf = 0; nf < 8; nf++) {
                unsigned bb[2];
                bb[0] = Vs[kk * 8 + q][nf * 8 + g];
                bb[1] = Vs[kk * 8 + q + 4][nf * 8 + g];
                mma_tf32(o[nf], p[kk], bb);
            }
        }
    }

    l0 += __shfl_xor_sync(0xffffffffu, l0, 1);
    l0 += __shfl_xor_sync(0xffffffffu, l0, 2);
    l1 += __shfl_xor_sync(0xffffffffu, l1, 1);
    l1 += __shfl_xor_sync(0xffffffffu, l1, 2);
    const float i0 = 1.f / l0, i1 = 1.f / l1;

    float* orow0 = g_attn + ((size_t)b * Ss + r0 + g) * Ee + h * 64;
    float* orow1 = g_attn + ((size_t)b * Ss + r0 + g + 8) * Ee + h * 64;
#pragma unroll
    for (int nf = 0; nf < 8; nf++) {
        int c = nf * 8 + 2 * q;
        *(float2*)(orow0 + c) = make_float2(o[nf][0] * i0, o[nf][1] * i0);
        *(float2*)(orow1 + c) = make_float2(o[nf][2] * i1, o[nf][3] * i1);
    }
}

// ---------------------------------------------------------------------------
extern "C" void kernel_launch(void* const* d_in, const int* in_sizes, int n_in,
                              void* d_out, int out_size)
{
    const float* hs    = (const float*)d_in[0];
    const float* wqkv  = (const float*)d_in[1];
    const float* bqkv  = (const float*)d_in[2];
    const float* wproj = (const float*)d_in[3];
    const float* bproj = (const float*)d_in[4];
    float* out = (float*)d_out;

    static int smem_set = 0;
    if (!smem_set) {
        cudaFuncSetAttribute(qkv_gemm_kernel,
                             cudaFuncAttributeMaxDynamicSharedMemorySize, SMEM_BYTES);
        cudaFuncSetAttribute(proj_gemm_kernel,
                             cudaFuncAttributeMaxDynamicSharedMemorySize, SMEM_BYTES);
        smem_set = 1;
    }

    dim3 g1(E3 / 128, (Bb * Ss) / 128);   // 24 x 32
    qkv_gemm_kernel<<<g1, 256, SMEM_BYTES>>>(hs, wqkv, bqkv);

    dim3 g2(Ss / 64, Bb * Hh);            // 32 x 32
    attn_mma_kernel<<<g2, 128>>>();

    dim3 g3(Ee / 128, (Bb * Ss) / 128);   // 8 x 32
    proj_gemm_kernel<<<g3, 256, SMEM_BYTES>>>(wproj, bproj, out);
}